// round 3
// baseline (speedup 1.0000x reference)
#include <cuda_runtime.h>
#include <cuda_bf16.h>

// Problem shape (fixed by dataset): B=32, S=4096, D=1024
#define B_ 32
#define S_ 4096
#define D_ 1024
#define ROWS (B_ * S_)            // 131072
#define ROWS_PER_BLK 8            // one warp per row, 8 warps/block
#define K1_GRID (ROWS / ROWS_PER_BLK)   // 16384
#define K2_THREADS 512

// Scratch (no allocations allowed anywhere)
__device__ float g_scores[ROWS];        // 512 KB
__device__ float g_partials[K1_GRID];   // 64 KB

__device__ __forceinline__ float warp_sum(float v) {
    #pragma unroll
    for (int o = 16; o > 0; o >>= 1) v += __shfl_xor_sync(0xFFFFFFFFu, v, o);
    return v;
}
__device__ __forceinline__ float warp_max(float v) {
    #pragma unroll
    for (int o = 16; o > 0; o >>= 1) v = fmaxf(v, __shfl_xor_sync(0xFFFFFFFFu, v, o));
    return v;
}

// K1: per-row dot(key_row, query_b) + global sum-of-squares partials.
// One warp per row. 1024 floats = 256 float4 per row; each lane does 8 float4.
__global__ __launch_bounds__(ROWS_PER_BLK * 32) void k1_dot_sumsq(
    const float* __restrict__ key, const float* __restrict__ query)
{
    const int warp = threadIdx.x >> 5;
    const int lane = threadIdx.x & 31;
    const int row  = blockIdx.x * ROWS_PER_BLK + warp;
    const int b    = row >> 12;               // row / S_

    const float4* __restrict__ k4 = reinterpret_cast<const float4*>(key) + (size_t)row * (D_ / 4);
    const float4* __restrict__ q4 = reinterpret_cast<const float4*>(query) + (size_t)b * (D_ / 4);

    // Load query first (L2/L1-resident after first rows of this batch),
    // then issue all 8 key LDG.128 back-to-back for max MLP.
    float4 qv[8];
    #pragma unroll
    for (int k = 0; k < 8; ++k) qv[k] = q4[lane + k * 32];
    float4 kv[8];
    #pragma unroll
    for (int k = 0; k < 8; ++k) kv[k] = k4[lane + k * 32];

    float dot = 0.f, ss = 0.f;
    #pragma unroll
    for (int k = 0; k < 8; ++k) {
        dot = fmaf(kv[k].x, qv[k].x, dot); dot = fmaf(kv[k].y, qv[k].y, dot);
        dot = fmaf(kv[k].z, qv[k].z, dot); dot = fmaf(kv[k].w, qv[k].w, dot);
        ss  = fmaf(kv[k].x, kv[k].x, ss);  ss  = fmaf(kv[k].y, kv[k].y, ss);
        ss  = fmaf(kv[k].z, kv[k].z, ss);  ss  = fmaf(kv[k].w, kv[k].w, ss);
    }
    dot = warp_sum(dot);
    ss  = warp_sum(ss);

    if (lane == 0) g_scores[row] = dot;

    __shared__ float s_ss[ROWS_PER_BLK];
    if (lane == 0) s_ss[warp] = ss;
    __syncthreads();
    if (threadIdx.x == 0) {
        float t = 0.f;
        #pragma unroll
        for (int i = 0; i < ROWS_PER_BLK; ++i) t += s_ss[i];
        g_partials[blockIdx.x] = t;
    }
}

// K2: one block per batch row. Deterministic reduce of partials, then masked
// softmax over the row's 4096 scores.
__global__ __launch_bounds__(K2_THREADS) void k2_softmax(
    const int* __restrict__ seq_lens, float* __restrict__ out)
{
    __shared__ float sh[S_];                  // 16 KB scaled scores / exps
    __shared__ float red[K2_THREADS / 32];    // 16 warps
    __shared__ float s_bcast;

    const int b    = blockIdx.x;
    const int tid  = threadIdx.x;
    const int lane = tid & 31;
    const int wid  = tid >> 5;

    // --- 1) total sum of squares (fixed order -> deterministic) ---
    float t = 0.f;
    for (int i = tid; i < K1_GRID; i += K2_THREADS) t += g_partials[i];
    t = warp_sum(t);
    if (lane == 0) red[wid] = t;
    __syncthreads();
    if (wid == 0) {
        float v = (lane < K2_THREADS / 32) ? red[lane] : 0.f;
        v = warp_sum(v);
        if (lane == 0) s_bcast = rsqrtf(v);   // 1/denom
    }
    __syncthreads();
    const float inv_denom = s_bcast;
    const int len = seq_lens[b];
    const float* __restrict__ sc = g_scores + (size_t)b * S_;

    // --- 2) scale + masked max ---
    float m = -3.4e38f;
    for (int i = tid; i < S_; i += K2_THREADS) {
        float v = sc[i] * inv_denom;
        sh[i] = v;
        if (i < len) m = fmaxf(m, v);
    }
    m = warp_max(m);
    __syncthreads();                           // red[] reuse guard
    if (lane == 0) red[wid] = m;
    __syncthreads();
    if (wid == 0) {
        float v = (lane < K2_THREADS / 32) ? red[lane] : -3.4e38f;
        v = warp_max(v);
        if (lane == 0) s_bcast = v;
    }
    __syncthreads();
    const float mx = s_bcast;

    // --- 3) masked exp (cached back to sh) + sum ---
    float sum = 0.f;
    for (int i = tid; i < S_; i += K2_THREADS) {
        float e = (i < len) ? __expf(sh[i] - mx) : 0.f;
        sh[i] = e;
        sum += e;
    }
    sum = warp_sum(sum);
    __syncthreads();                           // red[] reuse guard
    if (lane == 0) red[wid] = sum;
    __syncthreads();
    if (wid == 0) {
        float v = (lane < K2_THREADS / 32) ? red[lane] : 0.f;
        v = warp_sum(v);
        if (lane == 0) s_bcast = 1.f / v;
    }
    __syncthreads();
    const float inv_sum = s_bcast;

    // --- 4) write p + 1e-15 ---
    float* __restrict__ o = out + (size_t)b * S_;
    for (int i = tid; i < S_; i += K2_THREADS)
        o[i] = sh[i] * inv_sum + 1e-15f;
}

extern "C" void kernel_launch(void* const* d_in, const int* in_sizes, int n_in,
                              void* d_out, int out_size)
{
    const float* key      = (const float*)d_in[0];
    const float* query    = (const float*)d_in[1];
    const int*   seq_lens = (const int*)d_in[2];
    float*       out      = (float*)d_out;

    k1_dot_sumsq<<<K1_GRID, ROWS_PER_BLK * 32>>>(key, query);
    k2_softmax<<<B_, K2_THREADS>>>(seq_lens, out);
}

// round 6
// speedup vs baseline: 1.0311x; 1.0311x over previous
#include <cuda_runtime.h>
#include <cuda_bf16.h>

// Problem shape (fixed by dataset): B=32, S=4096, D=1024
#define B_ 32
#define S_ 4096
#define D_ 1024
#define ROWS (B_ * S_)            // 131072
#define ROWS_PER_BLK 8            // one warp per row, 8 warps/block
#define K1_THREADS (ROWS_PER_BLK * 32)
#define K1_GRID (ROWS / ROWS_PER_BLK)   // 16384
#define K1B_THREADS 1024
#define K2_THREADS 1024

// Scratch (no allocations allowed anywhere; no persistent cross-launch state)
__device__ float g_scores[ROWS];        // 512 KB
__device__ float g_partials[K1_GRID];   // 64 KB
__device__ float g_inv_denom;           // written fresh by k1b every launch

__device__ __forceinline__ float warp_sum(float v) {
    #pragma unroll
    for (int o = 16; o > 0; o >>= 1) v += __shfl_xor_sync(0xFFFFFFFFu, v, o);
    return v;
}
__device__ __forceinline__ float warp_max(float v) {
    #pragma unroll
    for (int o = 16; o > 0; o >>= 1) v = fmaxf(v, __shfl_xor_sync(0xFFFFFFFFu, v, o));
    return v;
}

// K1: per-row dot(key_row, query_b) + per-block sum-of-squares partial.
// One warp per row; 8 LDG.128 per lane front-batched for MLP. (Same as the
// version that passed at 90.1us; only the downstream reduction moved.)
__global__ __launch_bounds__(K1_THREADS) void k1_dot_sumsq(
    const float* __restrict__ key, const float* __restrict__ query)
{
    const int warp = threadIdx.x >> 5;
    const int lane = threadIdx.x & 31;
    const int row  = blockIdx.x * ROWS_PER_BLK + warp;
    const int b    = row >> 12;               // row / S_

    const float4* __restrict__ k4 = reinterpret_cast<const float4*>(key) + (size_t)row * (D_ / 4);
    const float4* __restrict__ q4 = reinterpret_cast<const float4*>(query) + (size_t)b * (D_ / 4);

    float4 qv[8];
    #pragma unroll
    for (int k = 0; k < 8; ++k) qv[k] = q4[lane + k * 32];
    float4 kv[8];
    #pragma unroll
    for (int k = 0; k < 8; ++k) kv[k] = k4[lane + k * 32];

    float dot = 0.f, ss = 0.f;
    #pragma unroll
    for (int k = 0; k < 8; ++k) {
        dot = fmaf(kv[k].x, qv[k].x, dot); dot = fmaf(kv[k].y, qv[k].y, dot);
        dot = fmaf(kv[k].z, qv[k].z, dot); dot = fmaf(kv[k].w, qv[k].w, dot);
        ss  = fmaf(kv[k].x, kv[k].x, ss);  ss  = fmaf(kv[k].y, kv[k].y, ss);
        ss  = fmaf(kv[k].z, kv[k].z, ss);  ss  = fmaf(kv[k].w, kv[k].w, ss);
    }
    dot = warp_sum(dot);
    ss  = warp_sum(ss);

    if (lane == 0) g_scores[row] = dot;

    __shared__ float s_ss[ROWS_PER_BLK];
    if (lane == 0) s_ss[warp] = ss;
    __syncthreads();
    if (threadIdx.x == 0) {
        float t = 0.f;
        #pragma unroll
        for (int i = 0; i < ROWS_PER_BLK; ++i) t += s_ss[i];
        g_partials[blockIdx.x] = t;
    }
}

// K1b: single block reduces the 16384 partials -> inv_denom.
// Fixed per-thread index order + fixed tree -> bitwise deterministic.
__global__ __launch_bounds__(K1B_THREADS) void k1b_reduce()
{
    __shared__ float red[K1B_THREADS / 32];   // 32 warps
    const int tid  = threadIdx.x;
    const int lane = tid & 31;
    const int wid  = tid >> 5;

    // 16384 / 1024 = 16 float loads per thread; read as float4 for width.
    const float4* p4 = reinterpret_cast<const float4*>(g_partials);
    float t = 0.f;
    #pragma unroll
    for (int k = 0; k < 4; ++k) {
        float4 v = p4[tid + k * K1B_THREADS];
        t += (v.x + v.y) + (v.z + v.w);
    }
    t = warp_sum(t);
    if (lane == 0) red[wid] = t;
    __syncthreads();
    if (wid == 0) {
        float v = red[lane];                  // exactly 32 warps
        v = warp_sum(v);
        if (lane == 0) g_inv_denom = rsqrtf(v);
    }
}

// K2: one block per batch row; masked softmax over 4096 scores.
// 1024 threads, one float4 per thread; scores & partial sum live in registers.
__global__ __launch_bounds__(K2_THREADS) void k2_softmax(
    const int* __restrict__ seq_lens, float* __restrict__ out)
{
    __shared__ float red[K2_THREADS / 32];    // 32 warps
    __shared__ float s_bcast;

    const int b    = blockIdx.x;
    const int tid  = threadIdx.x;
    const int lane = tid & 31;
    const int wid  = tid >> 5;

    const float inv_denom = g_inv_denom;
    const int   len = seq_lens[b];
    const float4* __restrict__ sc4 =
        reinterpret_cast<const float4*>(g_scores + (size_t)b * S_);

    // --- 1) scale + masked max (one float4 per thread) ---
    float4 v = sc4[tid];
    v.x *= inv_denom; v.y *= inv_denom; v.z *= inv_denom; v.w *= inv_denom;
    const int base = tid * 4;
    float m = -3.4e38f;
    if (base + 0 < len) m = fmaxf(m, v.x);
    if (base + 1 < len) m = fmaxf(m, v.y);
    if (base + 2 < len) m = fmaxf(m, v.z);
    if (base + 3 < len) m = fmaxf(m, v.w);
    m = warp_max(m);
    if (lane == 0) red[wid] = m;
    __syncthreads();
    if (wid == 0) {
        float t = red[lane];                  // exactly 32 warps
        t = warp_max(t);
        if (lane == 0) s_bcast = t;
    }
    __syncthreads();
    const float mx = s_bcast;

    // --- 2) masked exp (registers) + sum ---
    float4 e;
    e.x = (base + 0 < len) ? __expf(v.x - mx) : 0.f;
    e.y = (base + 1 < len) ? __expf(v.y - mx) : 0.f;
    e.z = (base + 2 < len) ? __expf(v.z - mx) : 0.f;
    e.w = (base + 3 < len) ? __expf(v.w - mx) : 0.f;
    float sum = (e.x + e.y) + (e.z + e.w);
    sum = warp_sum(sum);
    __syncthreads();                           // red[] reuse guard
    if (lane == 0) red[wid] = sum;
    __syncthreads();
    if (wid == 0) {
        float t = red[lane];
        t = warp_sum(t);
        if (lane == 0) s_bcast = 1.f / t;
    }
    __syncthreads();
    const float inv_sum = s_bcast;

    // --- 3) write p + 1e-15 ---
    float4 o;
    o.x = e.x * inv_sum + 1e-15f;
    o.y = e.y * inv_sum + 1e-15f;
    o.z = e.z * inv_sum + 1e-15f;
    o.w = e.w * inv_sum + 1e-15f;
    reinterpret_cast<float4*>(out + (size_t)b * S_)[tid] = o;
}

extern "C" void kernel_launch(void* const* d_in, const int* in_sizes, int n_in,
                              void* d_out, int out_size)
{
    const float* key      = (const float*)d_in[0];
    const float* query    = (const float*)d_in[1];
    const int*   seq_lens = (const int*)d_in[2];
    float*       out      = (float*)d_out;

    k1_dot_sumsq<<<K1_GRID, K1_THREADS>>>(key, query);
    k1b_reduce<<<1, K1B_THREADS>>>();
    k2_softmax<<<B_, K2_THREADS>>>(seq_lens, out);
}